// round 1
// baseline (speedup 1.0000x reference)
#include <cuda_runtime.h>
#include <cuda_bf16.h>
#include <cstdint>

#define NROWS 8192
#define BHALF 4096
#define DIM   256

// ---------------- scratch (device globals; no allocation) ----------------
__device__ __nv_bfloat16 g_Xhi[NROWS * DIM];
__device__ __nv_bfloat16 g_Xlo[NROWS * DIM];
__device__ float  g_sq[NROWS];
__device__ float  g_colpart[64 * DIM];
__device__ float  g_c1;            // -g0 * log2(e)
__device__ double g_Wpart[64 * 64];

// ---------------- prep: per-row sq-norm + bf16 hi/lo split ----------------
__global__ void prep_rows(const float* __restrict__ s, const float* __restrict__ t) {
    int warp = threadIdx.x >> 5, lane = threadIdx.x & 31;
    int row  = blockIdx.x * 8 + warp;
    const float* src = (row < BHALF) ? (s + (size_t)row * DIM)
                                     : (t + (size_t)(row - BHALF) * DIM);
    float4 v0 = *(const float4*)(src + lane * 8);
    float4 v1 = *(const float4*)(src + lane * 8 + 4);
    float v[8] = {v0.x, v0.y, v0.z, v0.w, v1.x, v1.y, v1.z, v1.w};

    float sq = 0.f;
    unsigned hu[4], lu[4];
#pragma unroll
    for (int j = 0; j < 4; j++) {
        float a = v[2 * j], b = v[2 * j + 1];
        sq = fmaf(a, a, sq);
        sq = fmaf(b, b, sq);
        __nv_bfloat16 ha = __float2bfloat16(a);
        __nv_bfloat16 hb = __float2bfloat16(b);
        __nv_bfloat16 la = __float2bfloat16(a - __bfloat162float(ha));
        __nv_bfloat16 lb = __float2bfloat16(b - __bfloat162float(hb));
        hu[j] = (unsigned)__bfloat16_as_ushort(ha) | ((unsigned)__bfloat16_as_ushort(hb) << 16);
        lu[j] = (unsigned)__bfloat16_as_ushort(la) | ((unsigned)__bfloat16_as_ushort(lb) << 16);
    }
    size_t off = (size_t)row * DIM + lane * 8;
    *(uint4*)(g_Xhi + off) = make_uint4(hu[0], hu[1], hu[2], hu[3]);
    *(uint4*)(g_Xlo + off) = make_uint4(lu[0], lu[1], lu[2], lu[3]);

#pragma unroll
    for (int o = 16; o; o >>= 1) sq += __shfl_xor_sync(0xffffffffu, sq, o);
    if (lane == 0) g_sq[row] = sq;
}

// ---------------- prep: column partial sums (for ||sum_x||^2) ----------------
__global__ void prep_cols(const float* __restrict__ s, const float* __restrict__ t) {
    int d = threadIdx.x;           // 0..255
    int b = blockIdx.x;            // 0..63
    float acc = 0.f;
    for (int r = 0; r < 128; r++) {
        int row = b * 128 + r;
        const float* src = (row < BHALF) ? (s + (size_t)row * DIM)
                                         : (t + (size_t)(row - BHALF) * DIM);
        acc += src[d];
    }
    g_colpart[b * DIM + d] = acc;
}

// ---------------- prep: bandwidth scalar (analytic sum of distances) ----------------
__global__ void prep_scalar() {
    __shared__ double sh[256];
    int t = threadIdx.x;
    double S = 0.0;
    for (int i = 0; i < 32; i++) S += (double)g_sq[t + i * 256];
    double c = 0.0;
    for (int b = 0; b < 64; b++) c += (double)g_colpart[b * DIM + t];
    // per-thread contribution to sum of distances = 2n*S_t - 2*c_t^2
    sh[t] = 2.0 * (double)NROWS * S - 2.0 * c * c;
    __syncthreads();
    for (int o = 128; o; o >>= 1) {
        if (t < o) sh[t] += sh[t + o];
        __syncthreads();
    }
    if (t == 0) {
        double sumd = sh[0];
        double bw = ((double)NROWS * (double)NROWS - (double)NROWS) / sumd;
        bw *= 0.25;  // / 2^(NUM_KERNELS//2)
        g_c1 = (float)(-bw * 1.4426950408889634);  // -g0 * log2(e)
    }
}

// ---------------- main fused GEMM + RBF epilogue ----------------
__device__ __forceinline__ void mma16816(float* c, const uint32_t* a, const uint32_t* b) {
    asm volatile(
        "mma.sync.aligned.m16n8k16.row.col.f32.bf16.bf16.f32 "
        "{%0,%1,%2,%3},{%4,%5,%6,%7},{%8,%9},{%0,%1,%2,%3};"
        : "+f"(c[0]), "+f"(c[1]), "+f"(c[2]), "+f"(c[3])
        : "r"(a[0]), "r"(a[1]), "r"(a[2]), "r"(a[3]), "r"(b[0]), "r"(b[1]));
}

__device__ __forceinline__ float kern_entry(float sq2, float g, float c1) {
    float d = fmaxf(fmaf(-2.f, g, sq2), 0.f);
    float p = d * c1;
    float e;
    asm("ex2.approx.f32 %0, %1;" : "=f"(e) : "f"(p));
    float e2 = e * e, e4 = e2 * e2, e8 = e4 * e4, e16 = e8 * e8;
    return ((e + e2) + (e4 + e8)) + e16;   // = 5 * averaged kernel value
}

#define SS 40  // smem row stride in bf16 elements (32 data + 8 pad): conflict-free

__global__ __launch_bounds__(256) void mmd_main() {
    __shared__ __nv_bfloat16 sAh[128 * SS], sAl[128 * SS];
    __shared__ __nv_bfloat16 sBh[128 * SS], sBl[128 * SS];
    __shared__ float sSqA[128], sSqB[128];
    __shared__ double swr[8];

    int bm = blockIdx.y, bn = blockIdx.x;
    int tid = threadIdx.x;
    int warp = tid >> 5, lane = tid & 31;
    int wm = warp >> 1, wn = warp & 1;        // 4x2 warp grid, warp tile 32x64
    int lane4 = lane >> 2;                    // 0..7
    int q2 = (lane & 3) * 2;                  // 0,2,4,6

    if (tid < 128) sSqA[tid] = g_sq[bm * 128 + tid];
    else           sSqB[tid - 128] = g_sq[bn * 128 + (tid - 128)];

    float acc[2][8][4];
#pragma unroll
    for (int mf = 0; mf < 2; mf++)
#pragma unroll
        for (int nf = 0; nf < 8; nf++)
#pragma unroll
            for (int k = 0; k < 4; k++) acc[mf][nf][k] = 0.f;

    for (int kc = 0; kc < 8; kc++) {   // K = 256 in chunks of 32
        __syncthreads();
#pragma unroll
        for (int i = 0; i < 2; i++) {
            int idx = tid + i * 256;           // 0..511
            int row = idx >> 2;                // 0..127
            int seg = idx & 3;                 // 0..3
            size_t gA = (size_t)(bm * 128 + row) * DIM + kc * 32 + seg * 8;
            size_t gB = (size_t)(bn * 128 + row) * DIM + kc * 32 + seg * 8;
            int so = row * SS + seg * 8;
            *(uint4*)(sAh + so) = *(const uint4*)(g_Xhi + gA);
            *(uint4*)(sAl + so) = *(const uint4*)(g_Xlo + gA);
            *(uint4*)(sBh + so) = *(const uint4*)(g_Xhi + gB);
            *(uint4*)(sBl + so) = *(const uint4*)(g_Xlo + gB);
        }
        __syncthreads();

#pragma unroll
        for (int ks = 0; ks < 2; ks++) {       // two k16 steps per chunk
            int k0 = ks * 16 + q2;
            uint32_t ah[2][4], al[2][4], bh[8][2], bl[8][2];
#pragma unroll
            for (int mf = 0; mf < 2; mf++) {
                int r = (wm * 32 + mf * 16 + lane4) * SS;
                ah[mf][0] = *(const uint32_t*)(sAh + r + k0);
                ah[mf][1] = *(const uint32_t*)(sAh + r + 8 * SS + k0);
                ah[mf][2] = *(const uint32_t*)(sAh + r + k0 + 8);
                ah[mf][3] = *(const uint32_t*)(sAh + r + 8 * SS + k0 + 8);
                al[mf][0] = *(const uint32_t*)(sAl + r + k0);
                al[mf][1] = *(const uint32_t*)(sAl + r + 8 * SS + k0);
                al[mf][2] = *(const uint32_t*)(sAl + r + k0 + 8);
                al[mf][3] = *(const uint32_t*)(sAl + r + 8 * SS + k0 + 8);
            }
#pragma unroll
            for (int nf = 0; nf < 8; nf++) {
                int c = (wn * 64 + nf * 8 + lane4) * SS;
                bh[nf][0] = *(const uint32_t*)(sBh + c + k0);
                bh[nf][1] = *(const uint32_t*)(sBh + c + k0 + 8);
                bl[nf][0] = *(const uint32_t*)(sBl + c + k0);
                bl[nf][1] = *(const uint32_t*)(sBl + c + k0 + 8);
            }
#pragma unroll
            for (int mf = 0; mf < 2; mf++)
#pragma unroll
                for (int nf = 0; nf < 8; nf++) {
                    mma16816(acc[mf][nf], ah[mf], bh[nf]);   // hi*hi
                    mma16816(acc[mf][nf], ah[mf], bl[nf]);   // hi*lo
                    mma16816(acc[mf][nf], al[mf], bh[nf]);   // lo*hi
                }
        }
    }

    // ------- fused epilogue: distances -> 5-kernel RBF sum via repeated squaring -------
    float c1 = g_c1;
    float wsum = 0.f;
    int r0 = wm * 32 + lane4;
#pragma unroll
    for (int mf = 0; mf < 2; mf++)
#pragma unroll
        for (int nf = 0; nf < 8; nf++) {
            int rA = r0 + mf * 16;
            int c0 = wn * 64 + nf * 8 + q2;
            float s0 = sSqA[rA], s1 = sSqA[rA + 8];
            float t0 = sSqB[c0], t1 = sSqB[c0 + 1];
            wsum += kern_entry(s0 + t0, acc[mf][nf][0], c1);
            wsum += kern_entry(s0 + t1, acc[mf][nf][1], c1);
            wsum += kern_entry(s1 + t0, acc[mf][nf][2], c1);
            wsum += kern_entry(s1 + t1, acc[mf][nf][3], c1);
        }

    // quadrant sign: + for s2s/t2t, - for s2t/t2s
    double w = (double)wsum;
    if ((bm < 32) != (bn < 32)) w = -w;
#pragma unroll
    for (int o = 16; o; o >>= 1) w += __shfl_down_sync(0xffffffffu, w, o);
    if (lane == 0) swr[warp] = w;
    __syncthreads();
    if (tid == 0) {
        double tot = 0.0;
#pragma unroll
        for (int i = 0; i < 8; i++) tot += swr[i];
        g_Wpart[bm * 64 + bn] = tot;   // overwritten every launch: deterministic
    }
}

// ---------------- final deterministic reduction ----------------
__global__ void final_reduce(float* out) {
    __shared__ double sh[256];
    int t = threadIdx.x;
    double a = 0.0;
    for (int i = 0; i < 16; i++) a += g_Wpart[t + i * 256];
    sh[t] = a;
    __syncthreads();
    for (int o = 128; o; o >>= 1) {
        if (t < o) sh[t] += sh[t + o];
        __syncthreads();
    }
    if (t == 0) out[0] = (float)(sh[0] / (5.0 * (double)BHALF * (double)BHALF));
}

// ---------------- launch ----------------
extern "C" void kernel_launch(void* const* d_in, const int* in_sizes, int n_in,
                              void* d_out, int out_size) {
    const float* s = (const float*)d_in[0];
    const float* t = (const float*)d_in[1];
    float* out = (float*)d_out;

    prep_rows<<<NROWS / 8, 256>>>(s, t);
    prep_cols<<<64, 256>>>(s, t);
    prep_scalar<<<1, 256>>>();
    dim3 grid(64, 64);
    mmd_main<<<grid, 256>>>();
    final_reduce<<<1, 256>>>(out);
}

// round 2
// speedup vs baseline: 2.0524x; 2.0524x over previous
#include <cuda_runtime.h>
#include <cuda_bf16.h>
#include <cstdint>

#define NROWS 8192
#define BHALF 4096
#define DIM   256
#define SS    40            // smem row stride (bf16 elems): conflict-free for LDSM
#define STAGE (128 * SS)    // elems per array per pipeline stage
#define NTILE 64
#define NBLK  2080          // upper-triangular 64x64 tile count
#define SMEM_BYTES (8 * STAGE * 2)   // 4 arrays x 2 stages x bf16 = 81920 B

// ---------------- scratch (device globals; no allocation) ----------------
__device__ __nv_bfloat16 g_Xhi[NROWS * DIM];
__device__ __nv_bfloat16 g_Xlo[NROWS * DIM];
__device__ float  g_sq[NROWS];
__device__ float  g_colpart[64 * DIM];
__device__ float  g_c1;            // -g0 * log2(e)
__device__ double g_Wpart[NBLK];

// ---------------- prep: per-row sq-norm + bf16 hi/lo split ----------------
__global__ void prep_rows(const float* __restrict__ s, const float* __restrict__ t) {
    int warp = threadIdx.x >> 5, lane = threadIdx.x & 31;
    int row  = blockIdx.x * 8 + warp;
    const float* src = (row < BHALF) ? (s + (size_t)row * DIM)
                                     : (t + (size_t)(row - BHALF) * DIM);
    float4 v0 = *(const float4*)(src + lane * 8);
    float4 v1 = *(const float4*)(src + lane * 8 + 4);
    float v[8] = {v0.x, v0.y, v0.z, v0.w, v1.x, v1.y, v1.z, v1.w};

    float sq = 0.f;
    unsigned hu[4], lu[4];
#pragma unroll
    for (int j = 0; j < 4; j++) {
        float a = v[2 * j], b = v[2 * j + 1];
        sq = fmaf(a, a, sq);
        sq = fmaf(b, b, sq);
        __nv_bfloat16 ha = __float2bfloat16(a);
        __nv_bfloat16 hb = __float2bfloat16(b);
        __nv_bfloat16 la = __float2bfloat16(a - __bfloat162float(ha));
        __nv_bfloat16 lb = __float2bfloat16(b - __bfloat162float(hb));
        hu[j] = (unsigned)__bfloat16_as_ushort(ha) | ((unsigned)__bfloat16_as_ushort(hb) << 16);
        lu[j] = (unsigned)__bfloat16_as_ushort(la) | ((unsigned)__bfloat16_as_ushort(lb) << 16);
    }
    size_t off = (size_t)row * DIM + lane * 8;
    *(uint4*)(g_Xhi + off) = make_uint4(hu[0], hu[1], hu[2], hu[3]);
    *(uint4*)(g_Xlo + off) = make_uint4(lu[0], lu[1], lu[2], lu[3]);

#pragma unroll
    for (int o = 16; o; o >>= 1) sq += __shfl_xor_sync(0xffffffffu, sq, o);
    if (lane == 0) g_sq[row] = sq;
}

// ---------------- prep: column partial sums (for ||sum_x||^2) ----------------
__global__ void prep_cols(const float* __restrict__ s, const float* __restrict__ t) {
    int d = threadIdx.x;           // 0..255
    int b = blockIdx.x;            // 0..63
    float acc = 0.f;
    for (int r = 0; r < 128; r++) {
        int row = b * 128 + r;
        const float* src = (row < BHALF) ? (s + (size_t)row * DIM)
                                         : (t + (size_t)(row - BHALF) * DIM);
        acc += src[d];
    }
    g_colpart[b * DIM + d] = acc;
}

// ---------------- prep: bandwidth scalar (analytic sum of distances) ----------------
__global__ void prep_scalar() {
    __shared__ double sh[256];
    int t = threadIdx.x;
    double S = 0.0;
    for (int i = 0; i < 32; i++) S += (double)g_sq[t + i * 256];
    double c = 0.0;
    for (int b = 0; b < 64; b++) c += (double)g_colpart[b * DIM + t];
    sh[t] = 2.0 * (double)NROWS * S - 2.0 * c * c;
    __syncthreads();
    for (int o = 128; o; o >>= 1) {
        if (t < o) sh[t] += sh[t + o];
        __syncthreads();
    }
    if (t == 0) {
        double sumd = sh[0];
        double bw = ((double)NROWS * (double)NROWS - (double)NROWS) / sumd;
        bw *= 0.25;  // / 2^(NUM_KERNELS//2)
        g_c1 = (float)(-bw * 1.4426950408889634);  // -g0 * log2(e)
    }
}

// ---------------- asm helpers ----------------
__device__ __forceinline__ void mma16816(float* c, const uint32_t* a, const uint32_t* b) {
    asm volatile(
        "mma.sync.aligned.m16n8k16.row.col.f32.bf16.bf16.f32 "
        "{%0,%1,%2,%3},{%4,%5,%6,%7},{%8,%9},{%0,%1,%2,%3};"
        : "+f"(c[0]), "+f"(c[1]), "+f"(c[2]), "+f"(c[3])
        : "r"(a[0]), "r"(a[1]), "r"(a[2]), "r"(a[3]), "r"(b[0]), "r"(b[1]));
}

__device__ __forceinline__ void ldm_x4(uint32_t* r, uint32_t addr) {
    asm volatile("ldmatrix.sync.aligned.m8n8.x4.shared.b16 {%0,%1,%2,%3}, [%4];"
                 : "=r"(r[0]), "=r"(r[1]), "=r"(r[2]), "=r"(r[3]) : "r"(addr));
}

__device__ __forceinline__ void cpa16(uint32_t d, const void* s) {
    asm volatile("cp.async.cg.shared.global [%0], [%1], 16;" :: "r"(d), "l"(s));
}

__device__ __forceinline__ float kern_entry(float sq2, float g, float c1) {
    float d = fmaxf(fmaf(-2.f, g, sq2), 0.f);
    float p = d * c1;
    float e;
    asm("ex2.approx.f32 %0, %1;" : "=f"(e) : "f"(p));
    float e2 = e * e, e4 = e2 * e2, e8 = e4 * e4, e16 = e8 * e8;
    return ((e + e2) + (e4 + e8)) + e16;   // = 5 * averaged kernel value
}

// ---------------- main fused GEMM + RBF epilogue (upper-triangular tiles) ----------------
__global__ __launch_bounds__(256, 2) void mmd_main() {
    extern __shared__ __nv_bfloat16 dsm[];
    __nv_bfloat16* sAh = dsm;
    __nv_bfloat16* sAl = dsm + 2 * STAGE;
    __nv_bfloat16* sBh = dsm + 4 * STAGE;
    __nv_bfloat16* sBl = dsm + 6 * STAGE;
    __shared__ float sSqA[128], sSqB[128];
    __shared__ double swr[8];

    // triangular tile decode: bm <= bn
    int rem = blockIdx.x, bm = 0;
    while (rem >= NTILE - bm) { rem -= NTILE - bm; bm++; }
    int bn = bm + rem;

    int tid = threadIdx.x;
    int warp = tid >> 5, lane = tid & 31;
    int wm = warp >> 1, wn = warp & 1;        // 4x2 warp grid, warp tile 32x64
    int lane4 = lane >> 2;                    // 0..7
    int q2 = (lane & 3) * 2;                  // 0,2,4,6
    int l8 = lane & 7;

    if (tid < 128) sSqA[tid] = g_sq[bm * 128 + tid];
    else           sSqB[tid - 128] = g_sq[bn * 128 + (tid - 128)];

    uint32_t uAh = (uint32_t)__cvta_generic_to_shared(sAh);
    uint32_t uAl = (uint32_t)__cvta_generic_to_shared(sAl);
    uint32_t uBh = (uint32_t)__cvta_generic_to_shared(sBh);
    uint32_t uBl = (uint32_t)__cvta_generic_to_shared(sBl);

    // ldmatrix per-lane element offsets (add mf*16*SS / p*16*SS and ks*16)
    int aoff = (wm * 32 + ((lane >> 3) & 1) * 8 + l8) * SS + (lane >> 4) * 8;
    int boff = (wn * 64 + ((lane >> 4) & 1) * 8 + l8) * SS + ((lane >> 3) & 1) * 8;

    float acc[2][8][4];
#pragma unroll
    for (int mf = 0; mf < 2; mf++)
#pragma unroll
        for (int nf = 0; nf < 8; nf++)
#pragma unroll
            for (int k = 0; k < 4; k++) acc[mf][nf][k] = 0.f;

    const size_t gAbase = (size_t)bm * 128 * DIM;
    const size_t gBbase = (size_t)bn * 128 * DIM;

    // cp.async loader for one 32-wide K chunk into stage st
#define LOAD_CHUNK(kc, st)                                                     \
    {                                                                          \
        _Pragma("unroll")                                                      \
        for (int it = 0; it < 2; it++) {                                       \
            int idx = tid + it * 256;                                          \
            int row = idx >> 2, seg = idx & 3;                                 \
            size_t go = (size_t)row * DIM + (kc) * 32 + seg * 8;               \
            uint32_t so = (uint32_t)((st) * STAGE + row * SS + seg * 8) * 2;   \
            cpa16(uAh + so, g_Xhi + gAbase + go);                              \
            cpa16(uAl + so, g_Xlo + gAbase + go);                              \
            cpa16(uBh + so, g_Xhi + gBbase + go);                              \
            cpa16(uBl + so, g_Xlo + gBbase + go);                              \
        }                                                                      \
        asm volatile("cp.async.commit_group;" ::: "memory");                   \
    }

    LOAD_CHUNK(0, 0);

    for (int kc = 0; kc < 8; kc++) {
        int st = kc & 1;
        if (kc < 7) {
            LOAD_CHUNK(kc + 1, st ^ 1);
            asm volatile("cp.async.wait_group 1;" ::: "memory");
        } else {
            asm volatile("cp.async.wait_group 0;" ::: "memory");
        }
        __syncthreads();

        uint32_t stB = (uint32_t)(st * STAGE) * 2;
#pragma unroll
        for (int ks = 0; ks < 2; ks++) {
            uint32_t kofs = stB + (uint32_t)(ks * 16) * 2;
            uint32_t ah[2][4], al[2][4];
#pragma unroll
            for (int mf = 0; mf < 2; mf++) {
                uint32_t aa = kofs + (uint32_t)((aoff + mf * 16 * SS) * 2);
                ldm_x4(ah[mf], uAh + aa);
                ldm_x4(al[mf], uAl + aa);
            }
#pragma unroll
            for (int p = 0; p < 4; p++) {
                uint32_t ba = kofs + (uint32_t)((boff + p * 16 * SS) * 2);
                uint32_t bh[4], bl[4];
                ldm_x4(bh, uBh + ba);
                ldm_x4(bl, uBl + ba);
#pragma unroll
                for (int mf = 0; mf < 2; mf++) {
                    mma16816(acc[mf][2 * p],     ah[mf], bh);      // hi*hi
                    mma16816(acc[mf][2 * p],     ah[mf], bl);      // hi*lo
                    mma16816(acc[mf][2 * p],     al[mf], bh);      // lo*hi
                    mma16816(acc[mf][2 * p + 1], ah[mf], bh + 2);
                    mma16816(acc[mf][2 * p + 1], ah[mf], bl + 2);
                    mma16816(acc[mf][2 * p + 1], al[mf], bh + 2);
                }
            }
        }
        __syncthreads();
    }

    // ------- fused epilogue: distances -> 5-kernel RBF sum via repeated squaring -------
    float c1 = g_c1;
    float wsum = 0.f;
    int r0 = wm * 32 + lane4;
#pragma unroll
    for (int mf = 0; mf < 2; mf++)
#pragma unroll
        for (int nf = 0; nf < 8; nf++) {
            int rA = r0 + mf * 16;
            int c0 = wn * 64 + nf * 8 + q2;
            float s0 = sSqA[rA], s1 = sSqA[rA + 8];
            float t0 = sSqB[c0], t1 = sSqB[c0 + 1];
            wsum += kern_entry(s0 + t0, acc[mf][nf][0], c1);
            wsum += kern_entry(s0 + t1, acc[mf][nf][1], c1);
            wsum += kern_entry(s1 + t0, acc[mf][nf][2], c1);
            wsum += kern_entry(s1 + t1, acc[mf][nf][3], c1);
        }

    // quadrant sign (+ for s2s/t2t, - for cross) and x2 for off-diagonal tiles
    double w = (double)wsum;
    if ((bm < 32) != (bn < 32)) w = -w;
    if (bm != bn) w *= 2.0;
#pragma unroll
    for (int o = 16; o; o >>= 1) w += __shfl_down_sync(0xffffffffu, w, o);
    if (lane == 0) swr[warp] = w;
    __syncthreads();
    if (tid == 0) {
        double tot = 0.0;
#pragma unroll
        for (int i = 0; i < 8; i++) tot += swr[i];
        g_Wpart[blockIdx.x] = tot;   // overwritten every launch: deterministic
    }
}

// ---------------- final deterministic reduction ----------------
__global__ void final_reduce(float* out) {
    __shared__ double sh[256];
    int t = threadIdx.x;
    double a = 0.0;
    for (int i = t; i < NBLK; i += 256) a += g_Wpart[i];
    sh[t] = a;
    __syncthreads();
    for (int o = 128; o; o >>= 1) {
        if (t < o) sh[t] += sh[t + o];
        __syncthreads();
    }
    if (t == 0) out[0] = (float)(sh[0] / (5.0 * (double)BHALF * (double)BHALF));
}

// ---------------- launch ----------------
extern "C" void kernel_launch(void* const* d_in, const int* in_sizes, int n_in,
                              void* d_out, int out_size) {
    const float* s = (const float*)d_in[0];
    const float* t = (const float*)d_in[1];
    float* out = (float*)d_out;

    cudaFuncSetAttribute(mmd_main, cudaFuncAttributeMaxDynamicSharedMemorySize, SMEM_BYTES);

    prep_rows<<<NROWS / 8, 256>>>(s, t);
    prep_cols<<<64, 256>>>(s, t);
    prep_scalar<<<1, 256>>>();
    mmd_main<<<NBLK, 256, SMEM_BYTES>>>();
    final_reduce<<<1, 256>>>(out);
}

// round 4
// speedup vs baseline: 2.5655x; 1.2500x over previous
#include <cuda_runtime.h>
#include <cuda_bf16.h>
#include <cstdint>

#define NROWS 8192
#define BHALF 4096
#define DIM   256
#define SS    40            // smem row stride (bf16 elems): conflict-free for LDSM
#define STAGE (128 * SS)    // elems per array per pipeline stage
#define NTILE 64
#define NBLK  2080          // upper-triangular 64x64 tile count
#define SMEM_BYTES (3 * STAGE * 2 * 2)   // 3 arrays x 2 stages x bf16 = 61440 B

// ---------------- scratch (device globals; no allocation) ----------------
__device__ __nv_bfloat16 g_Xhi[NROWS * DIM];
__device__ __nv_bfloat16 g_Xlo[NROWS * DIM];
__device__ float  g_sq[NROWS];
__device__ float  g_colpart[64 * DIM];
__device__ float  g_c1;            // -g0 * log2(e)
__device__ double g_Wpart[NBLK];

// ---------------- prep: per-row sq-norm + bf16 hi/lo split ----------------
__global__ void prep_rows(const float* __restrict__ s, const float* __restrict__ t) {
    int warp = threadIdx.x >> 5, lane = threadIdx.x & 31;
    int row  = blockIdx.x * 8 + warp;
    const float* src = (row < BHALF) ? (s + (size_t)row * DIM)
                                     : (t + (size_t)(row - BHALF) * DIM);
    float4 v0 = *(const float4*)(src + lane * 8);
    float4 v1 = *(const float4*)(src + lane * 8 + 4);
    float v[8] = {v0.x, v0.y, v0.z, v0.w, v1.x, v1.y, v1.z, v1.w};

    float sq = 0.f;
    unsigned hu[4], lu[4];
#pragma unroll
    for (int j = 0; j < 4; j++) {
        float a = v[2 * j], b = v[2 * j + 1];
        sq = fmaf(a, a, sq);
        sq = fmaf(b, b, sq);
        __nv_bfloat16 ha = __float2bfloat16(a);
        __nv_bfloat16 hb = __float2bfloat16(b);
        __nv_bfloat16 la = __float2bfloat16(a - __bfloat162float(ha));
        __nv_bfloat16 lb = __float2bfloat16(b - __bfloat162float(hb));
        hu[j] = (unsigned)__bfloat16_as_ushort(ha) | ((unsigned)__bfloat16_as_ushort(hb) << 16);
        lu[j] = (unsigned)__bfloat16_as_ushort(la) | ((unsigned)__bfloat16_as_ushort(lb) << 16);
    }
    size_t off = (size_t)row * DIM + lane * 8;
    *(uint4*)(g_Xhi + off) = make_uint4(hu[0], hu[1], hu[2], hu[3]);
    *(uint4*)(g_Xlo + off) = make_uint4(lu[0], lu[1], lu[2], lu[3]);

#pragma unroll
    for (int o = 16; o; o >>= 1) sq += __shfl_xor_sync(0xffffffffu, sq, o);
    if (lane == 0) g_sq[row] = sq;
}

// ---------------- prep: column partial sums (for ||sum_x||^2) ----------------
__global__ void prep_cols(const float* __restrict__ s, const float* __restrict__ t) {
    int d = threadIdx.x;           // 0..255
    int b = blockIdx.x;            // 0..63
    float acc = 0.f;
    for (int r = 0; r < 128; r++) {
        int row = b * 128 + r;
        const float* src = (row < BHALF) ? (s + (size_t)row * DIM)
                                         : (t + (size_t)(row - BHALF) * DIM);
        acc += src[d];
    }
    g_colpart[b * DIM + d] = acc;
}

// ---------------- prep: bandwidth scalar (analytic sum of distances) ----------------
__global__ void prep_scalar() {
    __shared__ double sh[256];
    int t = threadIdx.x;
    double S = 0.0;
    for (int i = 0; i < 32; i++) S += (double)g_sq[t + i * 256];
    double c = 0.0;
    for (int b = 0; b < 64; b++) c += (double)g_colpart[b * DIM + t];
    sh[t] = 2.0 * (double)NROWS * S - 2.0 * c * c;
    __syncthreads();
    for (int o = 128; o; o >>= 1) {
        if (t < o) sh[t] += sh[t + o];
        __syncthreads();
    }
    if (t == 0) {
        double sumd = sh[0];
        double bw = ((double)NROWS * (double)NROWS - (double)NROWS) / sumd;
        bw *= 0.25;  // / 2^(NUM_KERNELS//2)
        g_c1 = (float)(-bw * 1.4426950408889634);  // -g0 * log2(e)
    }
}

// ---------------- asm helpers ----------------
__device__ __forceinline__ void mma16816(float* c, const uint32_t* a, const uint32_t* b) {
    asm volatile(
        "mma.sync.aligned.m16n8k16.row.col.f32.bf16.bf16.f32 "
        "{%0,%1,%2,%3},{%4,%5,%6,%7},{%8,%9},{%0,%1,%2,%3};"
        : "+f"(c[0]), "+f"(c[1]), "+f"(c[2]), "+f"(c[3])
        : "r"(a[0]), "r"(a[1]), "r"(a[2]), "r"(a[3]), "r"(b[0]), "r"(b[1]));
}

__device__ __forceinline__ void ldm_x4(uint32_t* r, uint32_t addr) {
    asm volatile("ldmatrix.sync.aligned.m8n8.x4.shared.b16 {%0,%1,%2,%3}, [%4];"
                 : "=r"(r[0]), "=r"(r[1]), "=r"(r[2]), "=r"(r[3]) : "r"(addr));
}

__device__ __forceinline__ void cpa16(uint32_t d, const void* s) {
    asm volatile("cp.async.cg.shared.global [%0], [%1], 16;" :: "r"(d), "l"(s));
}

__device__ __forceinline__ float kern_entry(float sq2, float g, float c1) {
    float d = fmaxf(fmaf(-2.f, g, sq2), 0.f);
    float p = d * c1;
    float e;
    asm("ex2.approx.f32 %0, %1;" : "=f"(e) : "f"(p));
    float e2 = e * e, e4 = e2 * e2, e8 = e4 * e4, e16 = e8 * e8;
    return ((e + e2) + (e4 + e8)) + e16;   // = 5 * averaged kernel value
}

// ---------------- main fused GEMM + RBF epilogue (upper-triangular tiles) ----------------
__global__ __launch_bounds__(256, 2) void mmd_main() {
    extern __shared__ __nv_bfloat16 dsm[];
    __nv_bfloat16* sAh = dsm;                  // A hi (2 stages)
    __nv_bfloat16* sBh = dsm + 2 * STAGE;      // B hi (2 stages)
    __nv_bfloat16* sBl = dsm + 4 * STAGE;      // B lo (2 stages)
    __shared__ float sSqA[128], sSqB[128];
    __shared__ double swr[8];

    // triangular tile decode: bm <= bn
    int rem = blockIdx.x, bm = 0;
    while (rem >= NTILE - bm) { rem -= NTILE - bm; bm++; }
    int bn = bm + rem;

    int tid = threadIdx.x;
    int warp = tid >> 5, lane = tid & 31;
    int wm = warp >> 1, wn = warp & 1;        // 4x2 warp grid, warp tile 32x64
    int lane4 = lane >> 2;                    // 0..7
    int q2 = (lane & 3) * 2;                  // 0,2,4,6
    int l8 = lane & 7;

    if (tid < 128) sSqA[tid] = g_sq[bm * 128 + tid];
    else           sSqB[tid - 128] = g_sq[bn * 128 + (tid - 128)];

    uint32_t uAh = (uint32_t)__cvta_generic_to_shared(sAh);
    uint32_t uBh = (uint32_t)__cvta_generic_to_shared(sBh);
    uint32_t uBl = (uint32_t)__cvta_generic_to_shared(sBl);

    // ldmatrix per-lane element offsets (add mf*16*SS / p*16*SS and ks*16)
    int aoff = (wm * 32 + ((lane >> 3) & 1) * 8 + l8) * SS + (lane >> 4) * 8;
    int boff = (wn * 64 + ((lane >> 4) & 1) * 8 + l8) * SS + ((lane >> 3) & 1) * 8;

    float acc[2][8][4];
#pragma unroll
    for (int mf = 0; mf < 2; mf++)
#pragma unroll
        for (int nf = 0; nf < 8; nf++)
#pragma unroll
            for (int k = 0; k < 4; k++) acc[mf][nf][k] = 0.f;

    const size_t gAbase = (size_t)bm * 128 * DIM;
    const size_t gBbase = (size_t)bn * 128 * DIM;

    // cp.async loader for one 32-wide K chunk into stage st (Ah, Bh, Bl)
#define LOAD_CHUNK(kc, st)                                                     \
    {                                                                          \
        _Pragma("unroll")                                                      \
        for (int it = 0; it < 2; it++) {                                       \
            int idx = tid + it * 256;                                          \
            int row = idx >> 2, seg = idx & 3;                                 \
            size_t go = (size_t)row * DIM + (kc) * 32 + seg * 8;               \
            uint32_t so = (uint32_t)((st) * STAGE + row * SS + seg * 8) * 2;   \
            cpa16(uAh + so, g_Xhi + gAbase + go);                              \
            cpa16(uBh + so, g_Xhi + gBbase + go);                              \
            cpa16(uBl + so, g_Xlo + gBbase + go);                              \
        }                                                                      \
        asm volatile("cp.async.commit_group;" ::: "memory");                   \
    }

    LOAD_CHUNK(0, 0);

    for (int kc = 0; kc < 8; kc++) {
        int st = kc & 1;
        if (kc < 7) {
            LOAD_CHUNK(kc + 1, st ^ 1);
            asm volatile("cp.async.wait_group 1;" ::: "memory");
        } else {
            asm volatile("cp.async.wait_group 0;" ::: "memory");
        }
        __syncthreads();

        uint32_t stB = (uint32_t)(st * STAGE) * 2;
#pragma unroll
        for (int ks = 0; ks < 2; ks++) {
            uint32_t kofs = stB + (uint32_t)(ks * 16) * 2;
            uint32_t ah[2][4];
#pragma unroll
            for (int mf = 0; mf < 2; mf++) {
                uint32_t aa = kofs + (uint32_t)((aoff + mf * 16 * SS) * 2);
                ldm_x4(ah[mf], uAh + aa);
            }
#pragma unroll
            for (int p = 0; p < 4; p++) {
                uint32_t ba = kofs + (uint32_t)((boff + p * 16 * SS) * 2);
                uint32_t bh[4], bl[4];
                ldm_x4(bh, uBh + ba);
                ldm_x4(bl, uBl + ba);
                // term-major order: 4 independent accumulators between reuse
                mma16816(acc[0][2 * p],     ah[0], bh);       // hi*hi
                mma16816(acc[1][2 * p],     ah[1], bh);
                mma16816(acc[0][2 * p + 1], ah[0], bh + 2);
                mma16816(acc[1][2 * p + 1], ah[1], bh + 2);
                mma16816(acc[0][2 * p],     ah[0], bl);       // hi*lo
                mma16816(acc[1][2 * p],     ah[1], bl);
                mma16816(acc[0][2 * p + 1], ah[0], bl + 2);
                mma16816(acc[1][2 * p + 1], ah[1], bl + 2);
            }
        }
        __syncthreads();
    }

    // ------- fused epilogue: distances -> 5-kernel RBF sum via repeated squaring -------
    float c1 = g_c1;
    float wsum = 0.f;
    int r0 = wm * 32 + lane4;
#pragma unroll
    for (int mf = 0; mf < 2; mf++)
#pragma unroll
        for (int nf = 0; nf < 8; nf++) {
            int rA = r0 + mf * 16;
            int c0 = wn * 64 + nf * 8 + q2;
            float s0 = sSqA[rA], s1 = sSqA[rA + 8];
            float t0 = sSqB[c0], t1 = sSqB[c0 + 1];
            wsum += kern_entry(s0 + t0, acc[mf][nf][0], c1);
            wsum += kern_entry(s0 + t1, acc[mf][nf][1], c1);
            wsum += kern_entry(s1 + t0, acc[mf][nf][2], c1);
            wsum += kern_entry(s1 + t1, acc[mf][nf][3], c1);
        }

    // quadrant sign (+ for s2s/t2t, - for cross) and x2 for off-diagonal tiles
    double w = (double)wsum;
    if ((bm < 32) != (bn < 32)) w = -w;
    if (bm != bn) w *= 2.0;
#pragma unroll
    for (int o = 16; o; o >>= 1) w += __shfl_down_sync(0xffffffffu, w, o);
    if (lane == 0) swr[warp] = w;
    __syncthreads();
    if (tid == 0) {
        double tot = 0.0;
#pragma unroll
        for (int i = 0; i < 8; i++) tot += swr[i];
        g_Wpart[blockIdx.x] = tot;   // overwritten every launch: deterministic
    }
}

// ---------------- final deterministic reduction ----------------
__global__ void final_reduce(float* out) {
    __shared__ double sh[256];
    int t = threadIdx.x;
    double a = 0.0;
    for (int i = t; i < NBLK; i += 256) a += g_Wpart[i];
    sh[t] = a;
    __syncthreads();
    for (int o = 128; o; o >>= 1) {
        if (t < o) sh[t] += sh[t + o];
        __syncthreads();
    }
    if (t == 0) out[0] = (float)(sh[0] / (5.0 * (double)BHALF * (double)BHALF));
}

// ---------------- launch ----------------
extern "C" void kernel_launch(void* const* d_in, const int* in_sizes, int n_in,
                              void* d_out, int out_size) {
    const float* s = (const float*)d_in[0];
    const float* t = (const float*)d_in[1];
    float* out = (float*)d_out;

    cudaFuncSetAttribute(mmd_main, cudaFuncAttributeMaxDynamicSharedMemorySize, SMEM_BYTES);

    prep_rows<<<NROWS / 8, 256>>>(s, t);
    prep_cols<<<64, 256>>>(s, t);
    prep_scalar<<<1, 256>>>();
    mmd_main<<<NBLK, 256, SMEM_BYTES>>>();
    final_reduce<<<1, 256>>>(out);
}

// round 5
// speedup vs baseline: 2.6852x; 1.0466x over previous
#include <cuda_runtime.h>
#include <cuda_bf16.h>
#include <cstdint>

#define NROWS 8192
#define BHALF 4096
#define DIM   256
#define SS    72            // smem row stride (bf16): 64 data + 8 pad, conflict-free
#define STAGE (128 * SS)    // elems per array per pipeline stage (K=64 chunk)
#define NTILE 64
#define NBLK  2080          // upper-triangular 64x64 tile count
#define SMEM_BYTES (3 * 2 * STAGE * 2)   // 3 arrays x 2 stages x bf16 = 110592 B

// ---------------- scratch (device globals; no allocation) ----------------
__device__ __nv_bfloat16 g_Xhi[NROWS * DIM];
__device__ __nv_bfloat16 g_Xlo[NROWS * DIM];
__device__ float  g_sq[NROWS];
__device__ float  g_colpart[64 * DIM];
__device__ float  g_c1;            // -g0 * log2(e)
__device__ double g_Wpart[NBLK];

// ---------------- prep: per-row sq-norm + bf16 hi/lo split ----------------
__global__ void prep_rows(const float* __restrict__ s, const float* __restrict__ t) {
    int warp = threadIdx.x >> 5, lane = threadIdx.x & 31;
    int row  = blockIdx.x * 8 + warp;
    const float* src = (row < BHALF) ? (s + (size_t)row * DIM)
                                     : (t + (size_t)(row - BHALF) * DIM);
    float4 v0 = *(const float4*)(src + lane * 8);
    float4 v1 = *(const float4*)(src + lane * 8 + 4);
    float v[8] = {v0.x, v0.y, v0.z, v0.w, v1.x, v1.y, v1.z, v1.w};

    float sq = 0.f;
    unsigned hu[4], lu[4];
#pragma unroll
    for (int j = 0; j < 4; j++) {
        float a = v[2 * j], b = v[2 * j + 1];
        sq = fmaf(a, a, sq);
        sq = fmaf(b, b, sq);
        __nv_bfloat16 ha = __float2bfloat16(a);
        __nv_bfloat16 hb = __float2bfloat16(b);
        __nv_bfloat16 la = __float2bfloat16(a - __bfloat162float(ha));
        __nv_bfloat16 lb = __float2bfloat16(b - __bfloat162float(hb));
        hu[j] = (unsigned)__bfloat16_as_ushort(ha) | ((unsigned)__bfloat16_as_ushort(hb) << 16);
        lu[j] = (unsigned)__bfloat16_as_ushort(la) | ((unsigned)__bfloat16_as_ushort(lb) << 16);
    }
    size_t off = (size_t)row * DIM + lane * 8;
    *(uint4*)(g_Xhi + off) = make_uint4(hu[0], hu[1], hu[2], hu[3]);
    *(uint4*)(g_Xlo + off) = make_uint4(lu[0], lu[1], lu[2], lu[3]);

#pragma unroll
    for (int o = 16; o; o >>= 1) sq += __shfl_xor_sync(0xffffffffu, sq, o);
    if (lane == 0) g_sq[row] = sq;
}

// ---------------- prep: column partial sums (for ||sum_x||^2) ----------------
__global__ void prep_cols(const float* __restrict__ s, const float* __restrict__ t) {
    int d = threadIdx.x;           // 0..255
    int b = blockIdx.x;            // 0..63
    float acc = 0.f;
    for (int r = 0; r < 128; r++) {
        int row = b * 128 + r;
        const float* src = (row < BHALF) ? (s + (size_t)row * DIM)
                                         : (t + (size_t)(row - BHALF) * DIM);
        acc += src[d];
    }
    g_colpart[b * DIM + d] = acc;
}

// ---------------- prep: bandwidth scalar (analytic sum of distances) ----------------
__global__ void prep_scalar() {
    __shared__ double sh[256];
    int t = threadIdx.x;
    double S = 0.0;
    for (int i = 0; i < 32; i++) S += (double)g_sq[t + i * 256];
    double c = 0.0;
    for (int b = 0; b < 64; b++) c += (double)g_colpart[b * DIM + t];
    sh[t] = 2.0 * (double)NROWS * S - 2.0 * c * c;
    __syncthreads();
    for (int o = 128; o; o >>= 1) {
        if (t < o) sh[t] += sh[t + o];
        __syncthreads();
    }
    if (t == 0) {
        double sumd = sh[0];
        double bw = ((double)NROWS * (double)NROWS - (double)NROWS) / sumd;
        bw *= 0.25;  // / 2^(NUM_KERNELS//2)
        g_c1 = (float)(-bw * 1.4426950408889634);  // -g0 * log2(e)
    }
}

// ---------------- asm helpers ----------------
__device__ __forceinline__ void mma16816(float* c, const uint32_t* a, const uint32_t* b) {
    asm volatile(
        "mma.sync.aligned.m16n8k16.row.col.f32.bf16.bf16.f32 "
        "{%0,%1,%2,%3},{%4,%5,%6,%7},{%8,%9},{%0,%1,%2,%3};"
        : "+f"(c[0]), "+f"(c[1]), "+f"(c[2]), "+f"(c[3])
        : "r"(a[0]), "r"(a[1]), "r"(a[2]), "r"(a[3]), "r"(b[0]), "r"(b[1]));
}

__device__ __forceinline__ void ldm_x4(uint32_t* r, uint32_t addr) {
    asm volatile("ldmatrix.sync.aligned.m8n8.x4.shared.b16 {%0,%1,%2,%3}, [%4];"
                 : "=r"(r[0]), "=r"(r[1]), "=r"(r[2]), "=r"(r[3]) : "r"(addr));
}

__device__ __forceinline__ void cpa16(uint32_t d, const void* s) {
    asm volatile("cp.async.cg.shared.global [%0], [%1], 16;" :: "r"(d), "l"(s));
}

__device__ __forceinline__ float kern_entry(float sq2, float g, float c1) {
    float d = fmaxf(fmaf(-2.f, g, sq2), 0.f);
    float p = d * c1;
    float e;
    asm("ex2.approx.f32 %0, %1;" : "=f"(e) : "f"(p));
    float e2 = e * e, e4 = e2 * e2, e8 = e4 * e4, e16 = e8 * e8;
    return ((e + e2) + (e4 + e8)) + e16;   // = 5 * averaged kernel value
}

// ---------------- main fused GEMM + RBF epilogue (upper-triangular tiles) ----------------
// 128 threads = 4 warps (2x2), warp tile 64x64, CTA tile 128x128, K-chunk 64.
__global__ __launch_bounds__(128, 2) void mmd_main() {
    extern __shared__ __nv_bfloat16 dsm[];
    __nv_bfloat16* sAh = dsm;                  // A hi (2 stages)
    __nv_bfloat16* sBh = dsm + 2 * STAGE;      // B hi (2 stages)
    __nv_bfloat16* sBl = dsm + 4 * STAGE;      // B lo (2 stages)
    __shared__ float sSqA[128], sSqB[128];
    __shared__ double swr[4];

    // triangular tile decode: bm <= bn
    int rem = blockIdx.x, bm = 0;
    while (rem >= NTILE - bm) { rem -= NTILE - bm; bm++; }
    int bn = bm + rem;

    int tid = threadIdx.x;
    int warp = tid >> 5, lane = tid & 31;
    int wm = warp >> 1, wn = warp & 1;        // 2x2 warp grid, warp tile 64x64
    int lane4 = lane >> 2;                    // 0..7
    int q2 = (lane & 3) * 2;                  // 0,2,4,6
    int l8 = lane & 7;

    sSqA[tid] = g_sq[bm * 128 + tid];
    sSqB[tid] = g_sq[bn * 128 + tid];

    uint32_t uAh = (uint32_t)__cvta_generic_to_shared(sAh);
    uint32_t uBh = (uint32_t)__cvta_generic_to_shared(sBh);
    uint32_t uBl = (uint32_t)__cvta_generic_to_shared(sBl);

    // ldmatrix per-lane element offsets
    int aoff = (wm * 64 + ((lane >> 3) & 1) * 8 + l8) * SS + (lane >> 4) * 8;
    int boff = (wn * 64 + ((lane >> 4) & 1) * 8 + l8) * SS + ((lane >> 3) & 1) * 8;

    float acc[4][8][4];
#pragma unroll
    for (int mf = 0; mf < 4; mf++)
#pragma unroll
        for (int nf = 0; nf < 8; nf++)
#pragma unroll
            for (int k = 0; k < 4; k++) acc[mf][nf][k] = 0.f;

    const size_t gAbase = (size_t)bm * 128 * DIM;
    const size_t gBbase = (size_t)bn * 128 * DIM;

    // cp.async loader for one 64-wide K chunk into stage st (Ah, Bh, Bl)
#define LOAD_CHUNK(kc, st)                                                     \
    {                                                                          \
        _Pragma("unroll")                                                      \
        for (int it = 0; it < 8; it++) {                                       \
            int idx = tid + it * 128;          /* 0..1023 */                   \
            int row = idx >> 3, seg = idx & 7;                                 \
            size_t go = (size_t)row * DIM + (kc) * 64 + seg * 8;               \
            uint32_t so = (uint32_t)((st) * STAGE + row * SS + seg * 8) * 2;   \
            cpa16(uAh + so, g_Xhi + gAbase + go);                              \
            cpa16(uBh + so, g_Xhi + gBbase + go);                              \
            cpa16(uBl + so, g_Xlo + gBbase + go);                              \
        }                                                                      \
        asm volatile("cp.async.commit_group;" ::: "memory");                   \
    }

    LOAD_CHUNK(0, 0);
    LOAD_CHUNK(1, 1);

    for (int kc = 0; kc < 4; kc++) {   // K = 256 in chunks of 64
        int st = kc & 1;
        if (kc < 3) asm volatile("cp.async.wait_group 1;" ::: "memory");
        else        asm volatile("cp.async.wait_group 0;" ::: "memory");
        __syncthreads();

        uint32_t stB = (uint32_t)(st * STAGE) * 2;
#pragma unroll
        for (int ks = 0; ks < 4; ks++) {       // four k16 steps per chunk
            uint32_t kofs = stB + (uint32_t)(ks * 16) * 2;
            uint32_t ah[4][4];
#pragma unroll
            for (int mf = 0; mf < 4; mf++)
                ldm_x4(ah[mf], uAh + kofs + (uint32_t)((aoff + mf * 16 * SS) * 2));
#pragma unroll
            for (int p = 0; p < 4; p++) {
                uint32_t ba = kofs + (uint32_t)((boff + p * 16 * SS) * 2);
                uint32_t bh[4], bl[4];
                ldm_x4(bh, uBh + ba);
                ldm_x4(bl, uBl + ba);
                // reuse distance 8 between touches of the same accumulator
#pragma unroll
                for (int mf = 0; mf < 4; mf++) mma16816(acc[mf][2 * p],     ah[mf], bh);
#pragma unroll
                for (int mf = 0; mf < 4; mf++) mma16816(acc[mf][2 * p + 1], ah[mf], bh + 2);
#pragma unroll
                for (int mf = 0; mf < 4; mf++) mma16816(acc[mf][2 * p],     ah[mf], bl);
#pragma unroll
                for (int mf = 0; mf < 4; mf++) mma16816(acc[mf][2 * p + 1], ah[mf], bl + 2);
            }
        }
        __syncthreads();

        if (kc + 2 < 4) LOAD_CHUNK(kc + 2, st);
    }

    // ------- fused epilogue: distances -> 5-kernel RBF sum via repeated squaring -------
    float c1 = g_c1;
    float wsum = 0.f;
    int r0 = wm * 64 + lane4;
#pragma unroll
    for (int mf = 0; mf < 4; mf++)
#pragma unroll
        for (int nf = 0; nf < 8; nf++) {
            int rA = r0 + mf * 16;
            int c0 = wn * 64 + nf * 8 + q2;
            float s0 = sSqA[rA], s1 = sSqA[rA + 8];
            float t0 = sSqB[c0], t1 = sSqB[c0 + 1];
            wsum += kern_entry(s0 + t0, acc[mf][nf][0], c1);
            wsum += kern_entry(s0 + t1, acc[mf][nf][1], c1);
            wsum += kern_entry(s1 + t0, acc[mf][nf][2], c1);
            wsum += kern_entry(s1 + t1, acc[mf][nf][3], c1);
        }

    // quadrant sign (+ for s2s/t2t, - for cross) and x2 for off-diagonal tiles
    double w = (double)wsum;
    if ((bm < 32) != (bn < 32)) w = -w;
    if (bm != bn) w *= 2.0;
#pragma unroll
    for (int o = 16; o; o >>= 1) w += __shfl_down_sync(0xffffffffu, w, o);
    if (lane == 0) swr[warp] = w;
    __syncthreads();
    if (tid == 0) {
        double tot = swr[0] + swr[1] + swr[2] + swr[3];
        g_Wpart[blockIdx.x] = tot;   // overwritten every launch: deterministic
    }
}

// ---------------- final deterministic reduction ----------------
__global__ void final_reduce(float* out) {
    __shared__ double sh[256];
    int t = threadIdx.x;
    double a = 0.0;
    for (int i = t; i < NBLK; i += 256) a += g_Wpart[i];
    sh[t] = a;
    __syncthreads();
    for (int o = 128; o; o >>= 1) {
        if (t < o) sh[t] += sh[t + o];
        __syncthreads();
    }
    if (t == 0) out[0] = (float)(sh[0] / (5.0 * (double)BHALF * (double)BHALF));
}

// ---------------- launch ----------------
extern "C" void kernel_launch(void* const* d_in, const int* in_sizes, int n_in,
                              void* d_out, int out_size) {
    const float* s = (const float*)d_in[0];
    const float* t = (const float*)d_in[1];
    float* out = (float*)d_out;

    cudaFuncSetAttribute(mmd_main, cudaFuncAttributeMaxDynamicSharedMemorySize, SMEM_BYTES);

    prep_rows<<<NROWS / 8, 256>>>(s, t);
    prep_cols<<<64, 256>>>(s, t);
    prep_scalar<<<1, 256>>>();
    mmd_main<<<NBLK, 128, SMEM_BYTES>>>();
    final_reduce<<<1, 256>>>(out);
}

// round 6
// speedup vs baseline: 2.6858x; 1.0002x over previous
#include <cuda_runtime.h>
#include <cuda_bf16.h>
#include <cstdint>

#define NROWS 8192
#define BHALF 4096
#define DIM   256
#define SS    72            // smem row stride (bf16): 64 data + 8 pad, conflict-free
#define STAGE (128 * SS)    // elems per array per pipeline stage (K=64 chunk)
#define NTILE 64
#define NBLK  2080          // upper-triangular 64x64 tile count
#define SMEM_BYTES (3 * 2 * STAGE * 2)   // 3 arrays x 2 stages x bf16 = 110592 B

// ---------------- scratch (device globals; no allocation) ----------------
__device__ __nv_bfloat16 g_Xhi[NROWS * DIM];
__device__ __nv_bfloat16 g_Xlo[NROWS * DIM];
__device__ float  g_sq[NROWS];
__device__ float  g_colpart[64 * DIM];
__device__ float  g_c1;            // -g0 * log2(e)
__device__ double g_Wpart[NBLK];

// ---------------- prep: per-row sq-norm + bf16 hi/lo split ----------------
__global__ void prep_rows(const float* __restrict__ s, const float* __restrict__ t) {
    int warp = threadIdx.x >> 5, lane = threadIdx.x & 31;
    int row  = blockIdx.x * 8 + warp;
    const float* src = (row < BHALF) ? (s + (size_t)row * DIM)
                                     : (t + (size_t)(row - BHALF) * DIM);
    float4 v0 = *(const float4*)(src + lane * 8);
    float4 v1 = *(const float4*)(src + lane * 8 + 4);
    float v[8] = {v0.x, v0.y, v0.z, v0.w, v1.x, v1.y, v1.z, v1.w};

    float sq = 0.f;
    unsigned hu[4], lu[4];
#pragma unroll
    for (int j = 0; j < 4; j++) {
        float a = v[2 * j], b = v[2 * j + 1];
        sq = fmaf(a, a, sq);
        sq = fmaf(b, b, sq);
        __nv_bfloat16 ha = __float2bfloat16(a);
        __nv_bfloat16 hb = __float2bfloat16(b);
        __nv_bfloat16 la = __float2bfloat16(a - __bfloat162float(ha));
        __nv_bfloat16 lb = __float2bfloat16(b - __bfloat162float(hb));
        hu[j] = (unsigned)__bfloat16_as_ushort(ha) | ((unsigned)__bfloat16_as_ushort(hb) << 16);
        lu[j] = (unsigned)__bfloat16_as_ushort(la) | ((unsigned)__bfloat16_as_ushort(lb) << 16);
    }
    size_t off = (size_t)row * DIM + lane * 8;
    *(uint4*)(g_Xhi + off) = make_uint4(hu[0], hu[1], hu[2], hu[3]);
    *(uint4*)(g_Xlo + off) = make_uint4(lu[0], lu[1], lu[2], lu[3]);

#pragma unroll
    for (int o = 16; o; o >>= 1) sq += __shfl_xor_sync(0xffffffffu, sq, o);
    if (lane == 0) g_sq[row] = sq;
}

// ---------------- prep: column partial sums (for ||sum_x||^2) ----------------
__global__ void prep_cols(const float* __restrict__ s, const float* __restrict__ t) {
    int d = threadIdx.x;           // 0..255
    int b = blockIdx.x;            // 0..63
    float acc = 0.f;
    for (int r = 0; r < 128; r++) {
        int row = b * 128 + r;
        const float* src = (row < BHALF) ? (s + (size_t)row * DIM)
                                         : (t + (size_t)(row - BHALF) * DIM);
        acc += src[d];
    }
    g_colpart[b * DIM + d] = acc;
}

// ---------------- prep: bandwidth scalar (analytic sum of distances) ----------------
__global__ void prep_scalar() {
    __shared__ double sh[256];
    int t = threadIdx.x;
    double S = 0.0;
    for (int i = 0; i < 32; i++) S += (double)g_sq[t + i * 256];
    double c = 0.0;
    for (int b = 0; b < 64; b++) c += (double)g_colpart[b * DIM + t];
    sh[t] = 2.0 * (double)NROWS * S - 2.0 * c * c;
    __syncthreads();
    for (int o = 128; o; o >>= 1) {
        if (t < o) sh[t] += sh[t + o];
        __syncthreads();
    }
    if (t == 0) {
        double sumd = sh[0];
        double bw = ((double)NROWS * (double)NROWS - (double)NROWS) / sumd;
        bw *= 0.25;  // / 2^(NUM_KERNELS//2)
        g_c1 = (float)(-bw * 1.4426950408889634);  // -g0 * log2(e)
    }
}

// ---------------- asm helpers ----------------
__device__ __forceinline__ void mma16816(float* c, const uint32_t* a, const uint32_t* b) {
    asm volatile(
        "mma.sync.aligned.m16n8k16.row.col.f32.bf16.bf16.f32 "
        "{%0,%1,%2,%3},{%4,%5,%6,%7},{%8,%9},{%0,%1,%2,%3};"
        : "+f"(c[0]), "+f"(c[1]), "+f"(c[2]), "+f"(c[3])
        : "r"(a[0]), "r"(a[1]), "r"(a[2]), "r"(a[3]), "r"(b[0]), "r"(b[1]));
}

__device__ __forceinline__ void ldm_x4(uint32_t* r, uint32_t addr) {
    asm volatile("ldmatrix.sync.aligned.m8n8.x4.shared.b16 {%0,%1,%2,%3}, [%4];"
                 : "=r"(r[0]), "=r"(r[1]), "=r"(r[2]), "=r"(r[3]) : "r"(addr));
}

__device__ __forceinline__ void cpa16(uint32_t d, const void* s) {
    asm volatile("cp.async.cg.shared.global [%0], [%1], 16;" :: "r"(d), "l"(s));
}

__device__ __forceinline__ float kern_entry(float sq2, float g, float c1) {
    float d = fmaxf(fmaf(-2.f, g, sq2), 0.f);
    float p = d * c1;
    float e;
    asm("ex2.approx.f32 %0, %1;" : "=f"(e) : "f"(p));
    float e2 = e * e, e4 = e2 * e2, e8 = e4 * e4, e16 = e8 * e8;
    return ((e + e2) + (e4 + e8)) + e16;   // = 5 * averaged kernel value
}

// ---------------- main fused GEMM + RBF epilogue (upper-triangular tiles) ----------------
// 128 threads = 4 warps (2x2), warp tile 64x64, CTA tile 128x128, K-chunk 64.
__global__ __launch_bounds__(128, 2) void mmd_main() {
    extern __shared__ __nv_bfloat16 dsm[];
    __nv_bfloat16* sAh = dsm;                  // A hi (2 stages)
    __nv_bfloat16* sBh = dsm + 2 * STAGE;      // B hi (2 stages)
    __nv_bfloat16* sBl = dsm + 4 * STAGE;      // B lo (2 stages)
    __shared__ float sSqA[128], sSqB[128];
    __shared__ double swr[4];

    // triangular tile decode: bm <= bn
    int rem = blockIdx.x, bm = 0;
    while (rem >= NTILE - bm) { rem -= NTILE - bm; bm++; }
    int bn = bm + rem;

    int tid = threadIdx.x;
    int warp = tid >> 5, lane = tid & 31;
    int wm = warp >> 1, wn = warp & 1;        // 2x2 warp grid, warp tile 64x64
    int lane4 = lane >> 2;                    // 0..7
    int q2 = (lane & 3) * 2;                  // 0,2,4,6
    int l8 = lane & 7;

    sSqA[tid] = g_sq[bm * 128 + tid];
    sSqB[tid] = g_sq[bn * 128 + tid];

    uint32_t uAh = (uint32_t)__cvta_generic_to_shared(sAh);
    uint32_t uBh = (uint32_t)__cvta_generic_to_shared(sBh);
    uint32_t uBl = (uint32_t)__cvta_generic_to_shared(sBl);

    // ldmatrix per-lane element offsets
    int aoff = (wm * 64 + ((lane >> 3) & 1) * 8 + l8) * SS + (lane >> 4) * 8;
    int boff = (wn * 64 + ((lane >> 4) & 1) * 8 + l8) * SS + ((lane >> 3) & 1) * 8;

    float acc[4][8][4];
#pragma unroll
    for (int mf = 0; mf < 4; mf++)
#pragma unroll
        for (int nf = 0; nf < 8; nf++)
#pragma unroll
            for (int k = 0; k < 4; k++) acc[mf][nf][k] = 0.f;

    const size_t gAbase = (size_t)bm * 128 * DIM;
    const size_t gBbase = (size_t)bn * 128 * DIM;

    // cp.async loader for one 64-wide K chunk into stage st (Ah, Bh, Bl)
#define LOAD_CHUNK(kc, st)                                                     \
    {                                                                          \
        _Pragma("unroll")                                                      \
        for (int it = 0; it < 8; it++) {                                       \
            int idx = tid + it * 128;          /* 0..1023 */                   \
            int row = idx >> 3, seg = idx & 7;                                 \
            size_t go = (size_t)row * DIM + (kc) * 64 + seg * 8;               \
            uint32_t so = (uint32_t)((st) * STAGE + row * SS + seg * 8) * 2;   \
            cpa16(uAh + so, g_Xhi + gAbase + go);                              \
            cpa16(uBh + so, g_Xhi + gBbase + go);                              \
            cpa16(uBl + so, g_Xlo + gBbase + go);                              \
        }                                                                      \
        asm volatile("cp.async.commit_group;" ::: "memory");                   \
    }

    LOAD_CHUNK(0, 0);
    LOAD_CHUNK(1, 1);

    for (int kc = 0; kc < 4; kc++) {   // K = 256 in chunks of 64
        int st = kc & 1;
        if (kc < 3) asm volatile("cp.async.wait_group 1;" ::: "memory");
        else        asm volatile("cp.async.wait_group 0;" ::: "memory");
        __syncthreads();

        uint32_t stB = (uint32_t)(st * STAGE) * 2;
#pragma unroll
        for (int ks = 0; ks < 4; ks++) {       // four k16 steps per chunk
            uint32_t kofs = stB + (uint32_t)(ks * 16) * 2;
            uint32_t ah[4][4], bh[4][4], bl[4][4];
            // ---- batch ALL fragment loads first: one exposed LDS latency ----
#pragma unroll
            for (int mf = 0; mf < 4; mf++)
                ldm_x4(ah[mf], uAh + kofs + (uint32_t)((aoff + mf * 16 * SS) * 2));
#pragma unroll
            for (int p = 0; p < 4; p++) {
                uint32_t ba = kofs + (uint32_t)((boff + p * 16 * SS) * 2);
                ldm_x4(bh[p], uBh + ba);
                ldm_x4(bl[p], uBl + ba);
            }
            // ---- 64 MMAs, term-major sweeps, acc reuse distance 16 ----
#pragma unroll
            for (int p = 0; p < 4; p++)
#pragma unroll
                for (int mf = 0; mf < 4; mf++) mma16816(acc[mf][2 * p],     ah[mf], bh[p]);
#pragma unroll
            for (int p = 0; p < 4; p++)
#pragma unroll
                for (int mf = 0; mf < 4; mf++) mma16816(acc[mf][2 * p + 1], ah[mf], bh[p] + 2);
#pragma unroll
            for (int p = 0; p < 4; p++)
#pragma unroll
                for (int mf = 0; mf < 4; mf++) mma16816(acc[mf][2 * p],     ah[mf], bl[p]);
#pragma unroll
            for (int p = 0; p < 4; p++)
#pragma unroll
                for (int mf = 0; mf < 4; mf++) mma16816(acc[mf][2 * p + 1], ah[mf], bl[p] + 2);
        }
        __syncthreads();

        if (kc + 2 < 4) LOAD_CHUNK(kc + 2, st);
    }

    // ------- fused epilogue: distances -> 5-kernel RBF sum via repeated squaring -------
    float c1 = g_c1;
    float wsum = 0.f;
    int r0 = wm * 64 + lane4;
#pragma unroll
    for (int mf = 0; mf < 4; mf++)
#pragma unroll
        for (int nf = 0; nf < 8; nf++) {
            int rA = r0 + mf * 16;
            int c0 = wn * 64 + nf * 8 + q2;
            float s0 = sSqA[rA], s1 = sSqA[rA + 8];
            float t0 = sSqB[c0], t1 = sSqB[c0 + 1];
            wsum += kern_entry(s0 + t0, acc[mf][nf][0], c1);
            wsum += kern_entry(s0 + t1, acc[mf][nf][1], c1);
            wsum += kern_entry(s1 + t0, acc[mf][nf][2], c1);
            wsum += kern_entry(s1 + t1, acc[mf][nf][3], c1);
        }

    // quadrant sign (+ for s2s/t2t, - for cross) and x2 for off-diagonal tiles
    double w = (double)wsum;
    if ((bm < 32) != (bn < 32)) w = -w;
    if (bm != bn) w *= 2.0;
#pragma unroll
    for (int o = 16; o; o >>= 1) w += __shfl_down_sync(0xffffffffu, w, o);
    if (lane == 0) swr[warp] = w;
    __syncthreads();
    if (tid == 0) {
        double tot = swr[0] + swr[1] + swr[2] + swr[3];
        g_Wpart[blockIdx.x] = tot;   // overwritten every launch: deterministic
    }
}

// ---------------- final deterministic reduction ----------------
__global__ void final_reduce(float* out) {
    __shared__ double sh[256];
    int t = threadIdx.x;
    double a = 0.0;
    for (int i = t; i < NBLK; i += 256) a += g_Wpart[i];
    sh[t] = a;
    __syncthreads();
    for (int o = 128; o; o >>= 1) {
        if (t < o) sh[t] += sh[t + o];
        __syncthreads();
    }
    if (t == 0) out[0] = (float)(sh[0] / (5.0 * (double)BHALF * (double)BHALF));
}

// ---------------- launch ----------------
extern "C" void kernel_launch(void* const* d_in, const int* in_sizes, int n_in,
                              void* d_out, int out_size) {
    const float* s = (const float*)d_in[0];
    const float* t = (const float*)d_in[1];
    float* out = (float*)d_out;

    cudaFuncSetAttribute(mmd_main, cudaFuncAttributeMaxDynamicSharedMemorySize, SMEM_BYTES);

    prep_rows<<<NROWS / 8, 256>>>(s, t);
    prep_cols<<<64, 256>>>(s, t);
    prep_scalar<<<1, 256>>>();
    mmd_main<<<NBLK, 128, SMEM_BYTES>>>();
    final_reduce<<<1, 256>>>(out);
}

// round 7
// speedup vs baseline: 3.0877x; 1.1497x over previous
#include <cuda_runtime.h>
#include <cuda_fp16.h>
#include <cstdint>

#define NROWS 8192
#define BHALF 4096
#define DIM   256
#define SS    72            // smem row stride (fp16): 64 data + 8 pad, conflict-free
#define STAGE (128 * SS)    // elems per array per pipeline stage (K=64 chunk)
#define NTILE 64
#define NBLK  2080          // upper-triangular 64x64 tile count
#define SMEM_BYTES (2 * 2 * STAGE * 2)   // 2 arrays x 2 stages x fp16 = 73728 B
#define CB 256              // prep_cols blocks

// ---------------- scratch (device globals; no allocation) ----------------
__device__ __half g_Xh[NROWS * DIM];
__device__ float  g_sq[NROWS];
__device__ float  g_colpart[CB * DIM];
__device__ float  g_c1;            // -g0 * log2(e)
__device__ double g_Wpart[NBLK];

// ---------------- prep: per-row sq-norm + fp16 image ----------------
__global__ void prep_rows(const float* __restrict__ s, const float* __restrict__ t) {
    int warp = threadIdx.x >> 5, lane = threadIdx.x & 31;
    int row  = blockIdx.x * 8 + warp;
    const float* src = (row < BHALF) ? (s + (size_t)row * DIM)
                                     : (t + (size_t)(row - BHALF) * DIM);
    float4 v0 = *(const float4*)(src + lane * 8);
    float4 v1 = *(const float4*)(src + lane * 8 + 4);
    float v[8] = {v0.x, v0.y, v0.z, v0.w, v1.x, v1.y, v1.z, v1.w};

    float sq = 0.f;
    unsigned hu[4];
#pragma unroll
    for (int j = 0; j < 4; j++) {
        float a = v[2 * j], b = v[2 * j + 1];
        sq = fmaf(a, a, sq);
        sq = fmaf(b, b, sq);
        __half ha = __float2half_rn(a);
        __half hb = __float2half_rn(b);
        hu[j] = (unsigned)__half_as_ushort(ha) | ((unsigned)__half_as_ushort(hb) << 16);
    }
    size_t off = (size_t)row * DIM + lane * 8;
    *(uint4*)(g_Xh + off) = make_uint4(hu[0], hu[1], hu[2], hu[3]);

#pragma unroll
    for (int o = 16; o; o >>= 1) sq += __shfl_xor_sync(0xffffffffu, sq, o);
    if (lane == 0) g_sq[row] = sq;
}

// ---------------- prep: column partial sums (for ||sum_x||^2) ----------------
__global__ void prep_cols(const float* __restrict__ s, const float* __restrict__ t) {
    int d = threadIdx.x;           // 0..255
    int b = blockIdx.x;            // 0..CB-1
    float acc = 0.f;
#pragma unroll 4
    for (int r = 0; r < NROWS / CB; r++) {
        int row = b * (NROWS / CB) + r;
        const float* src = (row < BHALF) ? (s + (size_t)row * DIM)
                                         : (t + (size_t)(row - BHALF) * DIM);
        acc += src[d];
    }
    g_colpart[b * DIM + d] = acc;
}

// ---------------- prep: bandwidth scalar (analytic sum of distances) ----------------
__global__ void prep_scalar() {
    __shared__ double sh[256];
    int t = threadIdx.x;
    double S = 0.0;
    for (int i = 0; i < 32; i++) S += (double)g_sq[t + i * 256];
    double c = 0.0;
    for (int b = 0; b < CB; b++) c += (double)g_colpart[b * DIM + t];
    sh[t] = 2.0 * (double)NROWS * S - 2.0 * c * c;
    __syncthreads();
    for (int o = 128; o; o >>= 1) {
        if (t < o) sh[t] += sh[t + o];
        __syncthreads();
    }
    if (t == 0) {
        double sumd = sh[0];
        double bw = ((double)NROWS * (double)NROWS - (double)NROWS) / sumd;
        bw *= 0.25;  // / 2^(NUM_KERNELS//2)
        g_c1 = (float)(-bw * 1.4426950408889634);  // -g0 * log2(e)
    }
}

// ---------------- asm helpers ----------------
__device__ __forceinline__ void mma16816(float* c, const uint32_t* a, const uint32_t* b) {
    asm volatile(
        "mma.sync.aligned.m16n8k16.row.col.f32.f16.f16.f32 "
        "{%0,%1,%2,%3},{%4,%5,%6,%7},{%8,%9},{%0,%1,%2,%3};"
        : "+f"(c[0]), "+f"(c[1]), "+f"(c[2]), "+f"(c[3])
        : "r"(a[0]), "r"(a[1]), "r"(a[2]), "r"(a[3]), "r"(b[0]), "r"(b[1]));
}

__device__ __forceinline__ void ldm_x4(uint32_t* r, uint32_t addr) {
    asm volatile("ldmatrix.sync.aligned.m8n8.x4.shared.b16 {%0,%1,%2,%3}, [%4];"
                 : "=r"(r[0]), "=r"(r[1]), "=r"(r[2]), "=r"(r[3]) : "r"(addr));
}

__device__ __forceinline__ void cpa16(uint32_t d, const void* s) {
    asm volatile("cp.async.cg.shared.global [%0], [%1], 16;" :: "r"(d), "l"(s));
}

__device__ __forceinline__ float kern_entry(float sq2, float g, float c1) {
    float d = fmaxf(fmaf(-2.f, g, sq2), 0.f);
    float p = d * c1;
    float e;
    asm("ex2.approx.f32 %0, %1;" : "=f"(e) : "f"(p));
    float e2 = e * e, e4 = e2 * e2, e8 = e4 * e4, e16 = e8 * e8;
    return ((e + e2) + (e4 + e8)) + e16;   // = 5 * averaged kernel value
}

// ---------------- main fused GEMM + RBF epilogue (upper-triangular tiles) ----------------
// 256 threads = 8 warps (4x2), warp tile 32x64, CTA tile 128x128, K-chunk 64. ONE fp16 term.
__global__ __launch_bounds__(256, 2) void mmd_main() {
    extern __shared__ __half dsm[];
    __half* sA = dsm;                  // A fp16 (2 stages)
    __half* sB = dsm + 2 * STAGE;      // B fp16 (2 stages)
    __shared__ float sSqA[128], sSqB[128];
    __shared__ double swr[8];

    // triangular tile decode: bm <= bn
    int rem = blockIdx.x, bm = 0;
    while (rem >= NTILE - bm) { rem -= NTILE - bm; bm++; }
    int bn = bm + rem;

    int tid = threadIdx.x;
    int warp = tid >> 5, lane = tid & 31;
    int wm = warp >> 1, wn = warp & 1;        // 4x2 warp grid, warp tile 32x64
    int lane4 = lane >> 2;                    // 0..7
    int q2 = (lane & 3) * 2;                  // 0,2,4,6
    int l8 = lane & 7;

    if (tid < 128) sSqA[tid] = g_sq[bm * 128 + tid];
    else           sSqB[tid - 128] = g_sq[bn * 128 + (tid - 128)];

    uint32_t uA = (uint32_t)__cvta_generic_to_shared(sA);
    uint32_t uB = (uint32_t)__cvta_generic_to_shared(sB);

    // ldmatrix per-lane element offsets
    int aoff = (wm * 32 + ((lane >> 3) & 1) * 8 + l8) * SS + (lane >> 4) * 8;
    int boff = (wn * 64 + ((lane >> 4) & 1) * 8 + l8) * SS + ((lane >> 3) & 1) * 8;

    float acc[2][8][4];
#pragma unroll
    for (int mf = 0; mf < 2; mf++)
#pragma unroll
        for (int nf = 0; nf < 8; nf++)
#pragma unroll
            for (int k = 0; k < 4; k++) acc[mf][nf][k] = 0.f;

    const size_t gAbase = (size_t)bm * 128 * DIM;
    const size_t gBbase = (size_t)bn * 128 * DIM;

    // cp.async loader for one 64-wide K chunk into stage st (A, B)
#define LOAD_CHUNK(kc, st)                                                     \
    {                                                                          \
        _Pragma("unroll")                                                      \
        for (int it = 0; it < 4; it++) {                                       \
            int idx = tid + it * 256;          /* 0..1023 */                   \
            int row = idx >> 3, seg = idx & 7;                                 \
            size_t go = (size_t)row * DIM + (kc) * 64 + seg * 8;               \
            uint32_t so = (uint32_t)((st) * STAGE + row * SS + seg * 8) * 2;   \
            cpa16(uA + so, g_Xh + gAbase + go);                                \
            cpa16(uB + so, g_Xh + gBbase + go);                                \
        }                                                                      \
        asm volatile("cp.async.commit_group;" ::: "memory");                   \
    }

    LOAD_CHUNK(0, 0);
    LOAD_CHUNK(1, 1);

    for (int kc = 0; kc < 4; kc++) {   // K = 256 in chunks of 64
        int st = kc & 1;
        if (kc < 3) asm volatile("cp.async.wait_group 1;" ::: "memory");
        else        asm volatile("cp.async.wait_group 0;" ::: "memory");
        __syncthreads();

        uint32_t stB = (uint32_t)(st * STAGE) * 2;
#pragma unroll
        for (int ks = 0; ks < 4; ks++) {       // four k16 steps per chunk
            uint32_t kofs = stB + (uint32_t)(ks * 16) * 2;
            uint32_t ah[2][4], bh[4][4];
            // batch all fragment loads
#pragma unroll
            for (int mf = 0; mf < 2; mf++)
                ldm_x4(ah[mf], uA + kofs + (uint32_t)((aoff + mf * 16 * SS) * 2));
#pragma unroll
            for (int p = 0; p < 4; p++)
                ldm_x4(bh[p], uB + kofs + (uint32_t)((boff + p * 16 * SS) * 2));
            // 16 MMAs, reuse distance 4+
#pragma unroll
            for (int p = 0; p < 4; p++) {
#pragma unroll
                for (int mf = 0; mf < 2; mf++) mma16816(acc[mf][2 * p],     ah[mf], bh[p]);
#pragma unroll
                for (int mf = 0; mf < 2; mf++) mma16816(acc[mf][2 * p + 1], ah[mf], bh[p] + 2);
            }
        }
        __syncthreads();

        if (kc + 2 < 4) LOAD_CHUNK(kc + 2, st);
    }

    // ------- fused epilogue: distances -> 5-kernel RBF sum via repeated squaring -------
    float c1 = g_c1;
    float wsum = 0.f;
    int r0 = wm * 32 + lane4;
#pragma unroll
    for (int mf = 0; mf < 2; mf++)
#pragma unroll
        for (int nf = 0; nf < 8; nf++) {
            int rA = r0 + mf * 16;
            int c0 = wn * 64 + nf * 8 + q2;
            float s0 = sSqA[rA], s1 = sSqA[rA + 8];
            float t0 = sSqB[c0], t1 = sSqB[c0 + 1];
            wsum += kern_entry(s0 + t0, acc[mf][nf][0], c1);
            wsum += kern_entry(s0 + t1, acc[mf][nf][1], c1);
            wsum += kern_entry(s1 + t0, acc[mf][nf][2], c1);
            wsum += kern_entry(s1 + t1, acc[mf][nf][3], c1);
        }

    // quadrant sign (+ for s2s/t2t, - for cross) and x2 for off-diagonal tiles
    double w = (double)wsum;
    if ((bm < 32) != (bn < 32)) w = -w;
    if (bm != bn) w *= 2.0;
#pragma unroll
    for (int o = 16; o; o >>= 1) w += __shfl_down_sync(0xffffffffu, w, o);
    if (lane == 0) swr[warp] = w;
    __syncthreads();
    if (tid == 0) {
        double tot = 0.0;
#pragma unroll
        for (int i = 0; i < 8; i++) tot += swr[i];
        g_Wpart[blockIdx.x] = tot;   // overwritten every launch: deterministic
    }
}

// ---------------- final deterministic reduction ----------------
__global__ void final_reduce(float* out) {
    __shared__ double sh[256];
    int t = threadIdx.x;
    double a = 0.0;
    for (int i = t; i < NBLK; i += 256) a += g_Wpart[i];
    sh[t] = a;
    __syncthreads();
    for (int o = 128; o; o >>= 1) {
        if (t < o) sh[t] += sh[t + o];
        __syncthreads();
    }
    if (t == 0) out[0] = (float)(sh[0] / (5.0 * (double)BHALF * (double)BHALF));
}

// ---------------- launch ----------------
extern "C" void kernel_launch(void* const* d_in, const int* in_sizes, int n_in,
                              void* d_out, int out_size) {
    const float* s = (const float*)d_in[0];
    const float* t = (const float*)d_in[1];
    float* out = (float*)d_out;

    cudaFuncSetAttribute(mmd_main, cudaFuncAttributeMaxDynamicSharedMemorySize, SMEM_BYTES);

    prep_rows<<<NROWS / 8, 256>>>(s, t);
    prep_cols<<<CB, 256>>>(s, t);
    prep_scalar<<<1, 256>>>();
    mmd_main<<<NBLK, 256, SMEM_BYTES>>>();
    final_reduce<<<1, 256>>>(out);
}

// round 8
// speedup vs baseline: 3.1293x; 1.0135x over previous
#include <cuda_runtime.h>
#include <cuda_fp16.h>
#include <cstdint>

#define NROWS 8192
#define BHALF 4096
#define DIM   256
#define SS    72            // smem row stride (fp16): 64 data + 8 pad, conflict-free
#define STAGE (128 * SS)    // elems per array per pipeline stage (K=64 chunk)
#define NTILE 64
#define NBLK  2080          // upper-triangular 64x64 tile count
#define GRID  296           // persistent CTAs: 2 per SM
#define SMEM_BYTES (2 * 2 * STAGE * 2)   // 2 arrays x 2 stages x fp16 = 73728 B
#define CB 256              // column-partial blocks

// ---------------- scratch (device globals; no allocation) ----------------
__device__ __half g_Xh[NROWS * DIM];
__device__ float  g_sq[NROWS];
__device__ float  g_colpart[CB * DIM];
__device__ float  g_c1;            // -g0 * log2(e)
__device__ double g_Wpart[GRID];

// ---------------- fused prep: fp16 image + row sq-norms + column partials ----------------
// 256 blocks x 256 threads; block handles 32 rows (4 per warp).
__global__ void prep_fused(const float* __restrict__ s, const float* __restrict__ t) {
    __shared__ float scol[8][256];
    int warp = threadIdx.x >> 5, lane = threadIdx.x & 31;
    int tid = threadIdx.x;

    float colsum[8] = {0.f, 0.f, 0.f, 0.f, 0.f, 0.f, 0.f, 0.f};
#pragma unroll
    for (int i = 0; i < 4; i++) {
        int row = blockIdx.x * 32 + warp * 4 + i;
        const float* src = (row < BHALF) ? (s + (size_t)row * DIM)
                                         : (t + (size_t)(row - BHALF) * DIM);
        float4 v0 = *(const float4*)(src + lane * 8);
        float4 v1 = *(const float4*)(src + lane * 8 + 4);
        float v[8] = {v0.x, v0.y, v0.z, v0.w, v1.x, v1.y, v1.z, v1.w};

        float sq = 0.f;
        unsigned hu[4];
#pragma unroll
        for (int j = 0; j < 4; j++) {
            float a = v[2 * j], b = v[2 * j + 1];
            sq = fmaf(a, a, sq);
            sq = fmaf(b, b, sq);
            colsum[2 * j]     += a;
            colsum[2 * j + 1] += b;
            hu[j] = (unsigned)__half_as_ushort(__float2half_rn(a)) |
                    ((unsigned)__half_as_ushort(__float2half_rn(b)) << 16);
        }
        *(uint4*)(g_Xh + (size_t)row * DIM + lane * 8) = make_uint4(hu[0], hu[1], hu[2], hu[3]);
#pragma unroll
        for (int o = 16; o; o >>= 1) sq += __shfl_xor_sync(0xffffffffu, sq, o);
        if (lane == 0) g_sq[row] = sq;
    }
#pragma unroll
    for (int j = 0; j < 8; j++) scol[warp][lane * 8 + j] = colsum[j];
    __syncthreads();
    float a = 0.f;
#pragma unroll
    for (int w = 0; w < 8; w++) a += scol[w][tid];
    g_colpart[blockIdx.x * DIM + tid] = a;
}

// ---------------- prep: bandwidth scalar (analytic sum of distances) ----------------
__global__ void prep_scalar() {
    __shared__ double sh[256];
    int t = threadIdx.x;
    double S = 0.0;
    for (int i = 0; i < 32; i++) S += (double)g_sq[t + i * 256];
    double c = 0.0;
    for (int b = 0; b < CB; b++) c += (double)g_colpart[b * DIM + t];
    sh[t] = 2.0 * (double)NROWS * S - 2.0 * c * c;
    __syncthreads();
    for (int o = 128; o; o >>= 1) {
        if (t < o) sh[t] += sh[t + o];
        __syncthreads();
    }
    if (t == 0) {
        double sumd = sh[0];
        double bw = ((double)NROWS * (double)NROWS - (double)NROWS) / sumd;
        bw *= 0.25;  // / 2^(NUM_KERNELS//2)
        g_c1 = (float)(-bw * 1.4426950408889634);  // -g0 * log2(e)
    }
}

// ---------------- asm helpers ----------------
__device__ __forceinline__ void mma16816(float* c, const uint32_t* a, const uint32_t* b) {
    asm volatile(
        "mma.sync.aligned.m16n8k16.row.col.f32.f16.f16.f32 "
        "{%0,%1,%2,%3},{%4,%5,%6,%7},{%8,%9},{%0,%1,%2,%3};"
        : "+f"(c[0]), "+f"(c[1]), "+f"(c[2]), "+f"(c[3])
        : "r"(a[0]), "r"(a[1]), "r"(a[2]), "r"(a[3]), "r"(b[0]), "r"(b[1]));
}

__device__ __forceinline__ void ldm_x4(uint32_t* r, uint32_t addr) {
    asm volatile("ldmatrix.sync.aligned.m8n8.x4.shared.b16 {%0,%1,%2,%3}, [%4];"
                 : "=r"(r[0]), "=r"(r[1]), "=r"(r[2]), "=r"(r[3]) : "r"(addr));
}

__device__ __forceinline__ void cpa16(uint32_t d, const void* s) {
    asm volatile("cp.async.cg.shared.global [%0], [%1], 16;" :: "r"(d), "l"(s));
}

__device__ __forceinline__ float kern_entry(float sq2, float g, float c1) {
    float d = fmaxf(fmaf(-2.f, g, sq2), 0.f);
    float p = d * c1;
    float e;
    asm("ex2.approx.f32 %0, %1;" : "=f"(e) : "f"(p));
    float e2 = e * e, e4 = e2 * e2, e8 = e4 * e4, e16 = e8 * e8;
    return ((e + e2) + (e4 + e8)) + e16;   // = 5 * averaged kernel value
}

// ---------------- main: persistent fused GEMM + RBF epilogue ----------------
// 256 threads = 8 warps (4x2), warp tile 32x64, CTA tile 128x128, K-chunk 64.
// Persistent: each CTA owns a contiguous range of triangular tiles; cp.async
// ring runs continuously across tile boundaries so next-tile loads overlap
// the current tile's epilogue.
__global__ __launch_bounds__(256, 2) void mmd_main() {
    extern __shared__ __half dsm[];
    __half* sA = dsm;                  // A fp16 (2 stages)
    __half* sB = dsm + 2 * STAGE;      // B fp16 (2 stages)
    __shared__ float sSqA[128], sSqB[128];
    __shared__ double swr[8];

    int bx = blockIdx.x;
    int cnt   = (bx < 8) ? 8 : 7;                 // 2080 = 8*8 + 288*7
    int start = bx * 7 + min(bx, 8);

    // decode start tile -> (bm, bn), bm <= bn
    int rem = start, bm = 0;
    while (rem >= NTILE - bm) { rem -= NTILE - bm; bm++; }
    int bn = bm + rem;
    int bmL = bm, bnL = bn;                        // load-side tile coords

    int tid = threadIdx.x;
    int warp = tid >> 5, lane = tid & 31;
    int wm = warp >> 1, wn = warp & 1;
    int lane4 = lane >> 2;
    int q2 = (lane & 3) * 2;
    int l8 = lane & 7;

    uint32_t uA = (uint32_t)__cvta_generic_to_shared(sA);
    uint32_t uB = (uint32_t)__cvta_generic_to_shared(sB);

    int aoff = (wm * 32 + ((lane >> 3) & 1) * 8 + l8) * SS + (lane >> 4) * 8;
    int boff = (wn * 64 + ((lane >> 4) & 1) * 8 + l8) * SS + ((lane >> 3) & 1) * 8;

    float acc[2][8][4];

#define LOAD_CHUNK(bmv, bnv, kc, st)                                           \
    {                                                                          \
        const __half* gA = g_Xh + (size_t)(bmv) * 128 * DIM;                   \
        const __half* gB = g_Xh + (size_t)(bnv) * 128 * DIM;                   \
        _Pragma("unroll")                                                      \
        for (int it = 0; it < 4; it++) {                                       \
            int idx = tid + it * 256;                                          \
            int row = idx >> 3, seg = idx & 7;                                 \
            size_t go = (size_t)row * DIM + (kc) * 64 + seg * 8;               \
            uint32_t so = (uint32_t)((st) * STAGE + row * SS + seg * 8) * 2;   \
            cpa16(uA + so, gA + go);                                           \
            cpa16(uB + so, gB + go);                                           \
        }                                                                      \
        asm volatile("cp.async.commit_group;" ::: "memory");                   \
    }

    int G = cnt * 4;
    LOAD_CHUNK(bmL, bnL, 0, 0);
    LOAD_CHUNK(bmL, bnL, 1, 1);

    double accd = 0.0;
    float c1 = g_c1;

    for (int g = 0; g < G; g++) {
        int c = g & 3, st = g & 1;
        if (c == 0) {
            if (g > 0) { bn++; if (bn == NTILE) { bm++; bn = bm; } }
#pragma unroll
            for (int mf = 0; mf < 2; mf++)
#pragma unroll
                for (int nf = 0; nf < 8; nf++)
#pragma unroll
                    for (int k = 0; k < 4; k++) acc[mf][nf][k] = 0.f;
        }

        if (g + 1 < G) asm volatile("cp.async.wait_group 1;" ::: "memory");
        else           asm volatile("cp.async.wait_group 0;" ::: "memory");
        __syncthreads();

        uint32_t stB = (uint32_t)(st * STAGE) * 2;
#pragma unroll
        for (int ks = 0; ks < 4; ks++) {
            uint32_t kofs = stB + (uint32_t)(ks * 16) * 2;
            uint32_t ah[2][4], bh[4][4];
#pragma unroll
            for (int mf = 0; mf < 2; mf++)
                ldm_x4(ah[mf], uA + kofs + (uint32_t)((aoff + mf * 16 * SS) * 2));
#pragma unroll
            for (int p = 0; p < 4; p++)
                ldm_x4(bh[p], uB + kofs + (uint32_t)((boff + p * 16 * SS) * 2));
#pragma unroll
            for (int p = 0; p < 4; p++) {
#pragma unroll
                for (int mf = 0; mf < 2; mf++) mma16816(acc[mf][2 * p],     ah[mf], bh[p]);
#pragma unroll
                for (int mf = 0; mf < 2; mf++) mma16816(acc[mf][2 * p + 1], ah[mf], bh[p] + 2);
            }
        }
        __syncthreads();   // stage st free for reuse

        // issue loads for chunk g+2 (may belong to the next tile) BEFORE epilogue
        if (g + 2 < G) {
            int c2 = (g + 2) & 3;
            if (c2 == 0) { bnL++; if (bnL == NTILE) { bmL++; bnL = bmL; } }
            LOAD_CHUNK(bmL, bnL, c2, (g + 2) & 1);
        }

        if (c == 3) {   // tile complete: fused RBF epilogue
            if (tid < 128) sSqA[tid] = g_sq[bm * 128 + tid];
            else           sSqB[tid - 128] = g_sq[bn * 128 + (tid - 128)];
            __syncthreads();

            float wsum = 0.f;
            int r0 = wm * 32 + lane4;
#pragma unroll
            for (int mf = 0; mf < 2; mf++)
#pragma unroll
                for (int nf = 0; nf < 8; nf++) {
                    int rA = r0 + mf * 16;
                    int c0 = wn * 64 + nf * 8 + q2;
                    float s0 = sSqA[rA], s1 = sSqA[rA + 8];
                    float t0 = sSqB[c0], t1 = sSqB[c0 + 1];
                    wsum += kern_entry(s0 + t0, acc[mf][nf][0], c1);
                    wsum += kern_entry(s0 + t1, acc[mf][nf][1], c1);
                    wsum += kern_entry(s1 + t0, acc[mf][nf][2], c1);
                    wsum += kern_entry(s1 + t1, acc[mf][nf][3], c1);
                }

            double w = (double)wsum;
            if ((bm < 32) != (bn < 32)) w = -w;
            if (bm != bn) w *= 2.0;
            accd += w;
        }
    }

    // deterministic per-CTA reduction
#pragma unroll
    for (int o = 16; o; o >>= 1) accd += __shfl_down_sync(0xffffffffu, accd, o);
    if (lane == 0) swr[warp] = accd;
    __syncthreads();
    if (tid == 0) {
        double tot = 0.0;
#pragma unroll
        for (int i = 0; i < 8; i++) tot += swr[i];
        g_Wpart[bx] = tot;   // overwritten every launch: deterministic
    }
}

// ---------------- final deterministic reduction ----------------
__global__ void final_reduce(float* out) {
    __shared__ double sh[256];
    int t = threadIdx.x;
    double a = (t < GRID) ? g_Wpart[t] : 0.0;
    if (t + 256 < GRID) a += g_Wpart[t + 256];
    sh[t] = a;
    __syncthreads();
    for (int o = 128; o; o >>= 1) {
        if (t < o) sh[t] += sh[t + o];
        __syncthreads();
    }
    if (t == 0) out[0] = (float)(sh[0] / (5.0 * (double)BHALF * (double)BHALF));
}

// ---------------- launch ----------------
extern "C" void kernel_launch(void* const* d_in, const int* in_sizes, int n_in,
                              void* d_out, int out_size) {
    const float* s = (const float*)d_in[0];
    const float* t = (const float*)d_in[1];
    float* out = (float*)d_out;

    cudaFuncSetAttribute(mmd_main, cudaFuncAttributeMaxDynamicSharedMemorySize, SMEM_BYTES);

    prep_fused<<<CB, 256>>>(s, t);
    prep_scalar<<<1, 256>>>();
    mmd_main<<<GRID, 256, SMEM_BYTES>>>();
    final_reduce<<<1, 256>>>(out);
}